// round 1
// baseline (speedup 1.0000x reference)
#include <cuda_runtime.h>
#include <math.h>

#define NUM_L0 32
#define NUM_L1 16
#define NUM_L2 8
#define IN_W   120            // 32 + 48 + 40
#define N_VD   120            // C(16,2)
#define N_TD   28             // C(8,2)
#define OUT_W  204            // 32 + 16 + 8 + 120 + 28
#define EPS_N  1e-6f
#define WARPS_PER_BLOCK 8

// layout offsets in input row
#define VOFF   NUM_L0                       // 32:  vecs 16x3
#define TOFF   (NUM_L0 + 3 * NUM_L1)        // 80:  tens 8x5
// layout offsets in output row
#define O_VN   NUM_L0                       // 32
#define O_TN   (NUM_L0 + NUM_L1)            // 48
#define O_VD   (NUM_L0 + NUM_L1 + NUM_L2)   // 56
#define O_TD   (O_VD + N_VD)                // 176

__global__ __launch_bounds__(32 * WARPS_PER_BLOCK)
void invariant_extractor_kernel(const float* __restrict__ h,
                                float* __restrict__ out,
                                int n_atoms) {
    __shared__ float s_in [WARPS_PER_BLOCK][IN_W];
    __shared__ float s_out[WARPS_PER_BLOCK][OUT_W];

    const int w    = threadIdx.x >> 5;
    const int lane = threadIdx.x & 31;
    const int atom = blockIdx.x * WARPS_PER_BLOCK + w;
    if (atom >= n_atoms) return;

    float* si = s_in[w];
    float* so = s_out[w];

    // ---- coalesced load of the 120-float input row ----
    const float* row = h + (size_t)atom * IN_W;
    #pragma unroll
    for (int k = lane; k < IN_W; k += 32) si[k] = row[k];
    __syncwarp();

    // ---- scalars pass-through (all 32 lanes, region [0,32) never rewritten) ----
    so[lane] = si[lane];

    // ---- norms + in-place normalization ----
    if (lane < NUM_L1) {
        // vector channel `lane`
        const int b = VOFF + 3 * lane;
        float x = si[b], y = si[b + 1], z = si[b + 2];
        float nrm = sqrtf(x * x + y * y + z * z);
        nrm = fmaxf(nrm, EPS_N);
        so[O_VN + lane] = nrm;
        float inv = 1.0f / nrm;
        si[b] = x * inv; si[b + 1] = y * inv; si[b + 2] = z * inv;
    } else if (lane < NUM_L1 + NUM_L2) {
        // tensor channel t
        const int t = lane - NUM_L1;
        const int b = TOFF + 5 * t;
        float c0 = si[b], c1 = si[b + 1], c2 = si[b + 2], c3 = si[b + 3], c4 = si[b + 4];
        float nrm = sqrtf(c0 * c0 + c1 * c1 + c2 * c2 + c3 * c3 + c4 * c4);
        nrm = fmaxf(nrm, EPS_N);
        so[O_TN + t] = nrm;
        float inv = 1.0f / nrm;
        si[b] = c0 * inv; si[b + 1] = c1 * inv; si[b + 2] = c2 * inv;
        si[b + 3] = c3 * inv; si[b + 4] = c4 * inv;
    }
    __syncwarp();

    // ---- vector pair dots: 120 pairs, 4 per lane ----
    #pragma unroll
    for (int p = lane; p < N_VD; p += 32) {
        // recover (i, j) = p-th upper-triangle pair of a 16x16 matrix
        int i = 0, rem = p;
        while (rem >= NUM_L1 - 1 - i) { rem -= NUM_L1 - 1 - i; i++; }
        int j = i + 1 + rem;
        const float* a = si + VOFF + 3 * i;
        const float* b = si + VOFF + 3 * j;
        float d = a[0] * b[0] + a[1] * b[1] + a[2] * b[2];
        so[O_VD + p] = fminf(fmaxf(d, -1.0f), 1.0f);
    }

    // ---- tensor pair dots: 28 pairs, lanes 0..27 ----
    if (lane < N_TD) {
        int i = 0, rem = lane;
        while (rem >= NUM_L2 - 1 - i) { rem -= NUM_L2 - 1 - i; i++; }
        int j = i + 1 + rem;
        const float* a = si + TOFF + 5 * i;
        const float* b = si + TOFF + 5 * j;
        float d = a[0] * b[0] + a[1] * b[1] + a[2] * b[2] + a[3] * b[3] + a[4] * b[4];
        so[O_TD + lane] = fminf(fmaxf(d, -1.0f), 1.0f);
    }
    __syncwarp();

    // ---- coalesced store of the 204-float output row ----
    float* orow = out + (size_t)atom * OUT_W;
    #pragma unroll
    for (int k = lane; k < OUT_W; k += 32) orow[k] = so[k];
}

extern "C" void kernel_launch(void* const* d_in, const int* in_sizes, int n_in,
                              void* d_out, int out_size) {
    const float* h = (const float*)d_in[0];
    float* out = (float*)d_out;
    const int n_atoms = in_sizes[0] / IN_W;

    const int threads = 32 * WARPS_PER_BLOCK;
    const int blocks = (n_atoms + WARPS_PER_BLOCK - 1) / WARPS_PER_BLOCK;
    invariant_extractor_kernel<<<blocks, threads>>>(h, out, n_atoms);
}